// round 9
// baseline (speedup 1.0000x reference)
#include <cuda_runtime.h>
#include <cuda_bf16.h>
#include <cstdint>

#define NN 1024
#define DD 128

// ---------------- scratch (no allocations allowed) ----------------
__device__ float g_q[NN * DD];
__device__ float g_k[NN * DD];
__device__ float g_gi[NN * 3 * DD];

// progress flags (epoch-valued, monotonic => graph-replay-safe)
__device__ int g_flag[NN / 4 + 16];     // flag[c]==epoch when gi rows 4c..4c+3 ready
__device__ int g_epoch_att[NN / 4];     // per att+gi CTA launch counters
__device__ int g_epoch_gru;             // gru launch counter

// ---------------- helpers ----------------
__device__ __forceinline__ float tanh_apx(float x) {
    float y;
    asm("tanh.approx.f32 %0, %1;" : "=f"(y) : "f"(x));
    return y;
}
// sigmoid via one MUFU tanh (abs err ~1e-5; GRU is strongly contracting)
__device__ __forceinline__ float sig_apx(float x) {
    return fmaf(0.5f, tanh_apx(0.5f * x), 0.5f);
}

__device__ __forceinline__ unsigned long long ffma2(unsigned long long a,
                                                    unsigned long long b,
                                                    unsigned long long c) {
    unsigned long long d;
    asm("fma.rn.f32x2 %0, %1, %2, %3;" : "=l"(d) : "l"(a), "l"(b), "l"(c));
    return d;
}
__device__ __forceinline__ unsigned long long fadd2(unsigned long long a,
                                                    unsigned long long b) {
    unsigned long long d;
    asm("add.rn.f32x2 %0, %1, %2;" : "=l"(d) : "l"(a), "l"(b));
    return d;
}
__device__ __forceinline__ float f2lo(unsigned long long a) {
    return __uint_as_float((unsigned)(a & 0xffffffffull));
}
__device__ __forceinline__ float f2hi(unsigned long long a) {
    return __uint_as_float((unsigned)(a >> 32));
}

// block reductions for 384 threads (12 warps)
__device__ __forceinline__ float block_reduce_max(float v) {
    __shared__ float red[12];
    #pragma unroll
    for (int o = 16; o; o >>= 1) v = fmaxf(v, __shfl_xor_sync(0xffffffffu, v, o));
    if ((threadIdx.x & 31) == 0) red[threadIdx.x >> 5] = v;
    __syncthreads();
    float r = red[0];
    #pragma unroll
    for (int i = 1; i < 12; i++) r = fmaxf(r, red[i]);
    __syncthreads();
    return r;
}

__device__ __forceinline__ float block_reduce_sum(float v) {
    __shared__ float red[12];
    #pragma unroll
    for (int o = 16; o; o >>= 1) v += __shfl_xor_sync(0xffffffffu, v, o);
    if ((threadIdx.x & 31) == 0) red[threadIdx.x >> 5] = v;
    __syncthreads();
    float r = red[0];
    #pragma unroll
    for (int i = 1; i < 12; i++) r += red[i];
    __syncthreads();
    return r;
}

// ---------------- kernel 1: q = X@Wq^T, k = X@Wk^T ----------------
__global__ void __launch_bounds__(256) qk_kernel(const float* __restrict__ X,
                                                 const float* __restrict__ Wq,
                                                 const float* __restrict__ Wk) {
    __shared__ __align__(16) float xs[8][DD];
    const int n0 = blockIdx.x * 8;
    const int tid = threadIdx.x;
    for (int idx = tid; idx < 8 * DD; idx += 256)
        xs[idx >> 7][idx & 127] = X[(n0 + (idx >> 7)) * DD + (idx & 127)];
    __syncthreads();

    const int s = tid >> 7;
    const int d = tid & 127;
    const float4* W4 = (const float4*)((s ? Wk : Wq) + d * DD);
    float acc[8];
    #pragma unroll
    for (int r = 0; r < 8; r++) acc[r] = 0.0f;

    #pragma unroll 8
    for (int c = 0; c < 32; c++) {
        float4 w = W4[c];
        #pragma unroll
        for (int r = 0; r < 8; r++) {
            float4 x = *(const float4*)&xs[r][c * 4];
            acc[r] += w.x * x.x + w.y * x.y + w.z * x.z + w.w * x.w;
        }
    }
    float* dst = s ? g_k : g_q;
    #pragma unroll
    for (int r = 0; r < 8; r++) dst[(n0 + r) * DD + d] = acc[r];
}

// ---------------- kernel 2: fused attention + gi, flag per 4-row chunk -------
// 256 CTAs x 384 threads. CTA b: query rows i0=4b.
//   A: scores[r][j] = v . tanh(q_r + k_j),  j >= i0
//   B: softmax over suffix
//   C: att rows (context over keys) -> smem
//   D: gi rows = [X, att] @ w_ih^T + b_ih (+ b_hh fold for r/z) -> global
//   publish g_flag[b] = epoch
__global__ void __launch_bounds__(384) att_gi_kernel(const float* __restrict__ X,
                                                     const float* __restrict__ v,
                                                     const float* __restrict__ w_ih,
                                                     const float* __restrict__ b_ih,
                                                     const float* __restrict__ b_hh) {
    __shared__ __align__(16) float q_s[4][DD];
    __shared__ __align__(16) float v_s[DD];
    __shared__ float sc[4][NN];
    __shared__ float inv_s[4];
    __shared__ __align__(16) float x4_s[4][DD];
    __shared__ __align__(16) float att_s[4][DD];
    __shared__ float part1[4][DD];
    __shared__ float part2[4][DD];
    __shared__ int ep_s;

    const int blk = blockIdx.x;
    const int i0 = blk * 4;
    const int tid = threadIdx.x;

    if (tid == 0) ep_s = atomicAdd(&g_epoch_att[blk], 1) + 1;

    for (int idx = tid; idx < 4 * DD; idx += 384) {
        q_s[idx >> 7][idx & 127] = g_q[(i0 + (idx >> 7)) * DD + (idx & 127)];
        x4_s[idx >> 7][idx & 127] = X[(i0 + (idx >> 7)) * DD + (idx & 127)];
    }
    if (tid < DD) v_s[tid] = v[tid];
    __syncthreads();

    // ---- phase A: scores ----
    for (int j = i0 + tid; j < NN; j += 384) {
        const float4* kr = (const float4*)(g_k + j * DD);
        float a0 = 0.f, a1 = 0.f, a2 = 0.f, a3 = 0.f;
        #pragma unroll 4
        for (int c = 0; c < 32; c++) {
            float4 kk = kr[c];
            float4 vv = *(const float4*)&v_s[c * 4];
            float4 q0 = *(const float4*)&q_s[0][c * 4];
            float4 q1 = *(const float4*)&q_s[1][c * 4];
            float4 q2 = *(const float4*)&q_s[2][c * 4];
            float4 q3 = *(const float4*)&q_s[3][c * 4];
            a0 += vv.x * tanh_apx(q0.x + kk.x) + vv.y * tanh_apx(q0.y + kk.y)
                + vv.z * tanh_apx(q0.z + kk.z) + vv.w * tanh_apx(q0.w + kk.w);
            a1 += vv.x * tanh_apx(q1.x + kk.x) + vv.y * tanh_apx(q1.y + kk.y)
                + vv.z * tanh_apx(q1.z + kk.z) + vv.w * tanh_apx(q1.w + kk.w);
            a2 += vv.x * tanh_apx(q2.x + kk.x) + vv.y * tanh_apx(q2.y + kk.y)
                + vv.z * tanh_apx(q2.z + kk.z) + vv.w * tanh_apx(q2.w + kk.w);
            a3 += vv.x * tanh_apx(q3.x + kk.x) + vv.y * tanh_apx(q3.y + kk.y)
                + vv.z * tanh_apx(q3.z + kk.z) + vv.w * tanh_apx(q3.w + kk.w);
        }
        const int jj = j - i0;
        sc[0][jj] = a0; sc[1][jj] = a1; sc[2][jj] = a2; sc[3][jj] = a3;
    }
    __syncthreads();

    // ---- phase B: per-row softmax over the suffix ----
    const int L = NN - i0;
    for (int r = 0; r < 4; r++) {
        float m = -1e30f;
        for (int idx = tid; idx < L; idx += 384) m = fmaxf(m, sc[r][idx]);
        const float bm = block_reduce_max(m);
        float ssum = 0.f;
        for (int idx = tid; idx < L; idx += 384) {
            float e = (idx < r) ? 0.0f : __expf(sc[r][idx] - bm);
            sc[r][idx] = e;
            ssum += e;
        }
        const float bs = block_reduce_sum(ssum);
        if (tid == 0) inv_s[r] = 1.0f / bs;
    }
    __syncthreads();

    // ---- phase C: att rows -> att_s ----
    {
        const int d = tid & 127;
        const int s3 = tid >> 7;     // 0,1,2
        float a[4] = {0.f, 0.f, 0.f, 0.f};
        for (int j = i0 + s3; j < NN; j += 3) {
            const float x = X[j * DD + d];
            const int jj = j - i0;
            a[0] += sc[0][jj] * x;
            a[1] += sc[1][jj] * x;
            a[2] += sc[2][jj] * x;
            a[3] += sc[3][jj] * x;
        }
        if (s3 == 1) {
            #pragma unroll
            for (int r = 0; r < 4; r++) part1[r][d] = a[r];
        } else if (s3 == 2) {
            #pragma unroll
            for (int r = 0; r < 4; r++) part2[r][d] = a[r];
        }
        __syncthreads();
        if (s3 == 0) {
            #pragma unroll
            for (int r = 0; r < 4; r++)
                att_s[r][d] = (a[r] + part1[r][d] + part2[r][d]) * inv_s[r];
        }
        __syncthreads();
    }

    // ---- phase D: gi rows (one gate per thread, 4 time rows) ----
    {
        // in = [x4_s | att_s] read directly; w row streamed from L2
        const float4* w4 = (const float4*)(w_ih + tid * (2 * DD));
        float acc[4] = {0.f, 0.f, 0.f, 0.f};
        #pragma unroll 4
        for (int c = 0; c < 32; c++) {       // X half
            float4 w = w4[c];
            #pragma unroll
            for (int r = 0; r < 4; r++) {
                float4 iv = *(const float4*)&x4_s[r][c * 4];
                acc[r] += w.x * iv.x + w.y * iv.y + w.z * iv.z + w.w * iv.w;
            }
        }
        #pragma unroll 4
        for (int c = 0; c < 32; c++) {       // att half
            float4 w = w4[32 + c];
            #pragma unroll
            for (int r = 0; r < 4; r++) {
                float4 iv = *(const float4*)&att_s[r][c * 4];
                acc[r] += w.x * iv.x + w.y * iv.y + w.z * iv.z + w.w * iv.w;
            }
        }
        const float b = b_ih[tid] + ((tid < 2 * DD) ? b_hh[tid] : 0.0f);
        #pragma unroll
        for (int r = 0; r < 4; r++) g_gi[(i0 + r) * 384 + tid] = acc[r] + b;
    }

    __threadfence();
    __syncthreads();
    if (tid == 0) *(volatile int*)&g_flag[blk] = ep_s;
}

// ---------------- kernel 3: sequential GRU (overlapped consumer) -------------
// Warps 0-3  (t <  128): n-gate rows + serial tail (h kept in register).
// Warps 4-11 (t >= 128): r/z-gate rows, sigmoid pre-barrier.
// Thread 0 polls 4-row gi flags every 32 steps (window +9 chunks).
__global__ void __launch_bounds__(384, 1) gru_kernel(const float* __restrict__ w_hh,
                                                     const float* __restrict__ b_hh,
                                                     float* __restrict__ out) {
    __shared__ __align__(16) float h_s[DD];
    __shared__ float r_s[DD];
    __shared__ float z_s[DD];
    __shared__ int epoch_s;

    const int t = threadIdx.x;
    const bool is_n = (t < DD);
    const int g = t & 127;
    const int wrow = is_n ? (2 * DD + t) : (t - DD);   // own w_hh / gi row

    if (t == 0) epoch_s = atomicAdd(&g_epoch_gru, 1) + 1;

    unsigned long long w2[64];
    const unsigned long long* wp = (const unsigned long long*)(w_hh + wrow * DD);
    #pragma unroll
    for (int i = 0; i < 64; i++) w2[i] = wp[i];
    const float bh = is_n ? b_hh[2 * DD + t] : 0.0f;   // r/z bias folded in gi

    if (t < DD) h_s[t] = 0.0f;
    __syncthreads();
    const int epoch = epoch_s;

    const ulonglong2* h2 = (const ulonglong2*)h_s;

    // wait for gi chunks 0..9 (covers reads/prefetches for steps <= 39)
    if (t == 0) {
        volatile int* f = g_flag;
        for (int c = 0; c <= 9; c++)
            while (f[c] < epoch) __nanosleep(32);
    }
    __syncthreads();

    float gi_cur = g_gi[wrow];   // step 0 gate input for this thread's own row
    float hreg = 0.0f;           // n-threads: own h element in a register

    #pragma unroll 2
    for (int step = 0; step < NN; step++) {
        // s = bias + w_hh[wrow,:] . h   (packed f32x2 MACs, broadcast LDS of h)
        unsigned long long a0 = 0ull, a1 = 0ull, a2 = 0ull, a3 = 0ull;
        #pragma unroll
        for (int i = 0; i < 16; i++) {
            ulonglong2 hA = h2[2 * i];
            ulonglong2 hB = h2[2 * i + 1];
            a0 = ffma2(w2[4 * i + 0], hA.x, a0);
            a1 = ffma2(w2[4 * i + 1], hA.y, a1);
            a2 = ffma2(w2[4 * i + 2], hB.x, a2);
            a3 = ffma2(w2[4 * i + 3], hB.y, a3);
        }
        const unsigned long long p = fadd2(fadd2(a0, a1), fadd2(a2, a3));
        const float s = f2lo(p) + f2hi(p) + bh;

        if (!is_n) {
            // r/z warps: sigmoid locally, publish, arrive (non-blocking)
            const float val = sig_apx(gi_cur + s);
            if (t < 2 * DD) r_s[g] = val; else z_s[g] = val;
            asm volatile("bar.arrive 1, 384;" ::: "memory");
        } else {
            // n warps: wait for r/z, then the serial tail
            asm volatile("bar.sync 1, 384;" ::: "memory");
            const float rr  = r_s[g];
            const float zz  = z_s[g];
            const float nst = tanh_apx(fmaf(rr, s, gi_cur));   // s includes b_hh_n
            const float hv  = fmaf(zz, hreg - nst, nst);       // (1-z)n + z h
            hreg = hv;
            h_s[g] = hv;
            out[step * DD + g] = hv;
            // thread 0: advance the gi readiness window every 32 steps
            if ((step & 31) == 0 && step && t == 0) {
                const int c0 = step >> 2;
                const int c9 = (c0 + 9 < 256) ? (c0 + 9) : 255;
                volatile int* f = g_flag;
                for (int c = c0; c <= c9; c++)
                    while (f[c] < epoch) __nanosleep(32);
            }
        }
        // prefetch next step's gi inside the barrier shadow
        float gi_next = 0.0f;
        if (step + 1 < NN) gi_next = g_gi[(step + 1) * 384 + wrow];
        // everyone: h must be written before the next matvec
        asm volatile("bar.sync 2, 384;" ::: "memory");
        gi_cur = gi_next;
    }
}

// ---------------- launch ----------------
extern "C" void kernel_launch(void* const* d_in, const int* in_sizes, int n_in,
                              void* d_out, int out_size) {
    const float* X    = (const float*)d_in[0];
    const float* Wq   = (const float*)d_in[1];
    const float* Wk   = (const float*)d_in[2];
    const float* v    = (const float*)d_in[3];
    const float* w_ih = (const float*)d_in[4];
    const float* w_hh = (const float*)d_in[5];
    const float* b_ih = (const float*)d_in[6];
    const float* b_hh = (const float*)d_in[7];
    float* out = (float*)d_out;

    // fork: prologue (qk -> att+gi) on a side stream; GRU starts immediately on
    // the main stream and consumes gi chunks via epoch flags.
    cudaStream_t s2;
    cudaStreamCreateWithFlags(&s2, cudaStreamNonBlocking);
    cudaEvent_t e1, e2;
    cudaEventCreateWithFlags(&e1, cudaEventDisableTiming);
    cudaEventCreateWithFlags(&e2, cudaEventDisableTiming);

    cudaEventRecord(e1, 0);
    cudaStreamWaitEvent(s2, e1, 0);

    qk_kernel<<<NN / 8, 256, 0, s2>>>(X, Wq, Wk);
    att_gi_kernel<<<NN / 4, 384, 0, s2>>>(X, v, w_ih, b_ih, b_hh);
    cudaEventRecord(e2, s2);

    gru_kernel<<<1, 384>>>(w_hh, b_hh, out);

    cudaStreamWaitEvent(0, e2, 0);
}

// round 10
// speedup vs baseline: 1.1176x; 1.1176x over previous
#include <cuda_runtime.h>
#include <cuda_bf16.h>
#include <cstdint>

#define NN 1024
#define DD 128

// ---------------- scratch (no allocations allowed) ----------------
__device__ float g_q[NN * DD];
__device__ float g_k[NN * DD];
__device__ float g_gi[NN * 3 * DD];

// progress flags (epoch-valued, monotonic => graph-replay-safe)
__device__ int g_flag[NN / 4 + 16];     // flag[c]==epoch when gi rows 4c..4c+3 ready
__device__ int g_epoch_att[NN / 4];     // per att+gi CTA launch counters
__device__ int g_epoch_gru;             // gru launch counter

// ---------------- helpers ----------------
__device__ __forceinline__ float tanh_apx(float x) {
    float y;
    asm("tanh.approx.f32 %0, %1;" : "=f"(y) : "f"(x));
    return y;
}
// sigmoid via one MUFU tanh (abs err ~1e-5; GRU is strongly contracting)
__device__ __forceinline__ float sig_apx(float x) {
    return fmaf(0.5f, tanh_apx(0.5f * x), 0.5f);
}

__device__ __forceinline__ unsigned long long ffma2(unsigned long long a,
                                                    unsigned long long b,
                                                    unsigned long long c) {
    unsigned long long d;
    asm("fma.rn.f32x2 %0, %1, %2, %3;" : "=l"(d) : "l"(a), "l"(b), "l"(c));
    return d;
}
__device__ __forceinline__ unsigned long long fadd2(unsigned long long a,
                                                    unsigned long long b) {
    unsigned long long d;
    asm("add.rn.f32x2 %0, %1, %2;" : "=l"(d) : "l"(a), "l"(b));
    return d;
}
__device__ __forceinline__ float f2lo(unsigned long long a) {
    return __uint_as_float((unsigned)(a & 0xffffffffull));
}
__device__ __forceinline__ float f2hi(unsigned long long a) {
    return __uint_as_float((unsigned)(a >> 32));
}

// block reductions for 384 threads (12 warps)
__device__ __forceinline__ float block_reduce_max(float v) {
    __shared__ float red[12];
    #pragma unroll
    for (int o = 16; o; o >>= 1) v = fmaxf(v, __shfl_xor_sync(0xffffffffu, v, o));
    if ((threadIdx.x & 31) == 0) red[threadIdx.x >> 5] = v;
    __syncthreads();
    float r = red[0];
    #pragma unroll
    for (int i = 1; i < 12; i++) r = fmaxf(r, red[i]);
    __syncthreads();
    return r;
}

__device__ __forceinline__ float block_reduce_sum(float v) {
    __shared__ float red[12];
    #pragma unroll
    for (int o = 16; o; o >>= 1) v += __shfl_xor_sync(0xffffffffu, v, o);
    if ((threadIdx.x & 31) == 0) red[threadIdx.x >> 5] = v;
    __syncthreads();
    float r = red[0];
    #pragma unroll
    for (int i = 1; i < 12; i++) r += red[i];
    __syncthreads();
    return r;
}

// ---------------- kernel 1: q = X@Wq^T, k = X@Wk^T (4 rows per CTA) ---------
__global__ void __launch_bounds__(256) qk_kernel(const float* __restrict__ X,
                                                 const float* __restrict__ Wq,
                                                 const float* __restrict__ Wk) {
    __shared__ __align__(16) float xs[4][DD];
    const int n0 = blockIdx.x * 4;
    const int tid = threadIdx.x;
    for (int idx = tid; idx < 4 * DD; idx += 256)
        xs[idx >> 7][idx & 127] = X[(n0 + (idx >> 7)) * DD + (idx & 127)];
    __syncthreads();

    const int s = tid >> 7;
    const int d = tid & 127;
    const float4* W4 = (const float4*)((s ? Wk : Wq) + d * DD);
    float acc[4] = {0.f, 0.f, 0.f, 0.f};

    #pragma unroll 8
    for (int c = 0; c < 32; c++) {
        float4 w = W4[c];
        #pragma unroll
        for (int r = 0; r < 4; r++) {
            float4 x = *(const float4*)&xs[r][c * 4];
            acc[r] += w.x * x.x + w.y * x.y + w.z * x.z + w.w * x.w;
        }
    }
    float* dst = s ? g_k : g_q;
    #pragma unroll
    for (int r = 0; r < 4; r++) dst[(n0 + r) * DD + d] = acc[r];
}

// ---------------- kernel 2: fused attention + gi, flag per 4-row chunk -------
__global__ void __launch_bounds__(384) att_gi_kernel(const float* __restrict__ X,
                                                     const float* __restrict__ v,
                                                     const float* __restrict__ w_ih,
                                                     const float* __restrict__ b_ih,
                                                     const float* __restrict__ b_hh) {
    __shared__ __align__(16) float q_s[4][DD];
    __shared__ __align__(16) float v_s[DD];
    __shared__ float sc[4][NN];
    __shared__ float inv_s[4];
    __shared__ __align__(16) float x4_s[4][DD];
    __shared__ __align__(16) float att_s[4][DD];
    __shared__ float part1[4][DD];
    __shared__ float part2[4][DD];
    __shared__ int ep_s;

    const int blk = blockIdx.x;
    const int i0 = blk * 4;
    const int tid = threadIdx.x;

    if (tid == 0) ep_s = atomicAdd(&g_epoch_att[blk], 1) + 1;

    for (int idx = tid; idx < 4 * DD; idx += 384) {
        q_s[idx >> 7][idx & 127] = g_q[(i0 + (idx >> 7)) * DD + (idx & 127)];
        x4_s[idx >> 7][idx & 127] = X[(i0 + (idx >> 7)) * DD + (idx & 127)];
    }
    if (tid < DD) v_s[tid] = v[tid];
    __syncthreads();

    // ---- phase A: scores ----
    for (int j = i0 + tid; j < NN; j += 384) {
        const float4* kr = (const float4*)(g_k + j * DD);
        float a0 = 0.f, a1 = 0.f, a2 = 0.f, a3 = 0.f;
        #pragma unroll 4
        for (int c = 0; c < 32; c++) {
            float4 kk = kr[c];
            float4 vv = *(const float4*)&v_s[c * 4];
            float4 q0 = *(const float4*)&q_s[0][c * 4];
            float4 q1 = *(const float4*)&q_s[1][c * 4];
            float4 q2 = *(const float4*)&q_s[2][c * 4];
            float4 q3 = *(const float4*)&q_s[3][c * 4];
            a0 += vv.x * tanh_apx(q0.x + kk.x) + vv.y * tanh_apx(q0.y + kk.y)
                + vv.z * tanh_apx(q0.z + kk.z) + vv.w * tanh_apx(q0.w + kk.w);
            a1 += vv.x * tanh_apx(q1.x + kk.x) + vv.y * tanh_apx(q1.y + kk.y)
                + vv.z * tanh_apx(q1.z + kk.z) + vv.w * tanh_apx(q1.w + kk.w);
            a2 += vv.x * tanh_apx(q2.x + kk.x) + vv.y * tanh_apx(q2.y + kk.y)
                + vv.z * tanh_apx(q2.z + kk.z) + vv.w * tanh_apx(q2.w + kk.w);
            a3 += vv.x * tanh_apx(q3.x + kk.x) + vv.y * tanh_apx(q3.y + kk.y)
                + vv.z * tanh_apx(q3.z + kk.z) + vv.w * tanh_apx(q3.w + kk.w);
        }
        const int jj = j - i0;
        sc[0][jj] = a0; sc[1][jj] = a1; sc[2][jj] = a2; sc[3][jj] = a3;
    }
    __syncthreads();

    // ---- phase B: per-row softmax over the suffix ----
    const int L = NN - i0;
    for (int r = 0; r < 4; r++) {
        float m = -1e30f;
        for (int idx = tid; idx < L; idx += 384) m = fmaxf(m, sc[r][idx]);
        const float bm = block_reduce_max(m);
        float ssum = 0.f;
        for (int idx = tid; idx < L; idx += 384) {
            float e = (idx < r) ? 0.0f : __expf(sc[r][idx] - bm);
            sc[r][idx] = e;
            ssum += e;
        }
        const float bs = block_reduce_sum(ssum);
        if (tid == 0) inv_s[r] = 1.0f / bs;
    }
    __syncthreads();

    // ---- phase C: att rows -> att_s ----
    {
        const int d = tid & 127;
        const int s3 = tid >> 7;     // 0,1,2
        float a[4] = {0.f, 0.f, 0.f, 0.f};
        for (int j = i0 + s3; j < NN; j += 3) {
            const float x = X[j * DD + d];
            const int jj = j - i0;
            a[0] += sc[0][jj] * x;
            a[1] += sc[1][jj] * x;
            a[2] += sc[2][jj] * x;
            a[3] += sc[3][jj] * x;
        }
        if (s3 == 1) {
            #pragma unroll
            for (int r = 0; r < 4; r++) part1[r][d] = a[r];
        } else if (s3 == 2) {
            #pragma unroll
            for (int r = 0; r < 4; r++) part2[r][d] = a[r];
        }
        __syncthreads();
        if (s3 == 0) {
            #pragma unroll
            for (int r = 0; r < 4; r++)
                att_s[r][d] = (a[r] + part1[r][d] + part2[r][d]) * inv_s[r];
        }
        __syncthreads();
    }

    // ---- phase D: gi rows (one gate per thread, 4 time rows) ----
    {
        const float4* w4 = (const float4*)(w_ih + tid * (2 * DD));
        float acc[4] = {0.f, 0.f, 0.f, 0.f};
        #pragma unroll 4
        for (int c = 0; c < 32; c++) {       // X half
            float4 w = w4[c];
            #pragma unroll
            for (int r = 0; r < 4; r++) {
                float4 iv = *(const float4*)&x4_s[r][c * 4];
                acc[r] += w.x * iv.x + w.y * iv.y + w.z * iv.z + w.w * iv.w;
            }
        }
        #pragma unroll 4
        for (int c = 0; c < 32; c++) {       // att half
            float4 w = w4[32 + c];
            #pragma unroll
            for (int r = 0; r < 4; r++) {
                float4 iv = *(const float4*)&att_s[r][c * 4];
                acc[r] += w.x * iv.x + w.y * iv.y + w.z * iv.z + w.w * iv.w;
            }
        }
        const float b = b_ih[tid] + ((tid < 2 * DD) ? b_hh[tid] : 0.0f);
        #pragma unroll
        for (int r = 0; r < 4; r++) g_gi[(i0 + r) * 384 + tid] = acc[r] + b;
    }

    __threadfence();
    __syncthreads();
    if (tid == 0) *(volatile int*)&g_flag[blk] = ep_s;
}

// ---------------- kernel 3: sequential GRU (overlapped consumer) -------------
// Warps 0-3  (t <  128): n-gate rows + serial tail (h in register).
// Warps 4-11 (t >= 128): r/z-gate rows, sigmoid pre-barrier.
// Warp 11 polls gi flags (one flag per lane, parallel) in its dead time
// between bar.arrive(1) and bar.sync(2) -> poll is off the critical path.
__global__ void __launch_bounds__(384, 1) gru_kernel(const float* __restrict__ w_hh,
                                                     const float* __restrict__ b_hh,
                                                     float* __restrict__ out) {
    __shared__ __align__(16) float h_s[DD];
    __shared__ float r_s[DD];
    __shared__ float z_s[DD];
    __shared__ int epoch_s;

    const int t = threadIdx.x;
    const bool is_n = (t < DD);
    const int g = t & 127;
    const int wrow = is_n ? (2 * DD + t) : (t - DD);   // own w_hh / gi row

    if (t == 0) epoch_s = atomicAdd(&g_epoch_gru, 1) + 1;

    unsigned long long w2[64];
    const unsigned long long* wp = (const unsigned long long*)(w_hh + wrow * DD);
    #pragma unroll
    for (int i = 0; i < 64; i++) w2[i] = wp[i];
    const float bh = is_n ? b_hh[2 * DD + t] : 0.0f;   // r/z bias folded in gi

    if (t < DD) h_s[t] = 0.0f;
    __syncthreads();
    const int epoch = epoch_s;

    const ulonglong2* h2 = (const ulonglong2*)h_s;

    // initial wait: chunks 0..8 (covers steps 0..31 plus prefetch of row 32),
    // one flag per thread in parallel
    if (t <= 8) {
        volatile int* f = g_flag;
        while (f[t] < epoch) __nanosleep(32);
    }
    __syncthreads();

    float gi_cur = g_gi[wrow];   // step 0 gate input for this thread's own row
    float hreg = 0.0f;           // n-threads: own h element in a register

    for (int step = 0; step < NN; step++) {
        // prefetch next step's gi (hidden under the matvec)
        float gi_next = 0.0f;
        if (step + 1 < NN) gi_next = g_gi[(step + 1) * 384 + wrow];

        // s = bias + w_hh[wrow,:] . h   (packed f32x2 MACs, broadcast LDS of h)
        unsigned long long a0 = 0ull, a1 = 0ull, a2 = 0ull, a3 = 0ull;
        #pragma unroll
        for (int i = 0; i < 16; i++) {
            ulonglong2 hA = h2[2 * i];
            ulonglong2 hB = h2[2 * i + 1];
            a0 = ffma2(w2[4 * i + 0], hA.x, a0);
            a1 = ffma2(w2[4 * i + 1], hA.y, a1);
            a2 = ffma2(w2[4 * i + 2], hB.x, a2);
            a3 = ffma2(w2[4 * i + 3], hB.y, a3);
        }
        const unsigned long long p = fadd2(fadd2(a0, a1), fadd2(a2, a3));
        const float s = f2lo(p) + f2hi(p) + bh;

        if (!is_n) {
            // r/z warps: sigmoid locally, publish, arrive (non-blocking)
            const float val = sig_apx(gi_cur + s);
            if (t < 2 * DD) r_s[g] = val; else z_s[g] = val;
            asm volatile("bar.arrive 1, 384;" ::: "memory");
            // warp 11: advance the gi readiness window in its dead time
            if (t >= 352 && (step & 31) == 0 && step) {
                const int l = t - 352;
                if (l <= 8) {
                    int c = (step >> 2) + l;
                    if (c > 255) c = 255;
                    volatile int* f = g_flag;
                    while (f[c] < epoch) __nanosleep(32);
                }
            }
        } else {
            // n warps: wait for r/z, then the serial tail
            asm volatile("bar.sync 1, 384;" ::: "memory");
            const float rr  = r_s[g];
            const float zz  = z_s[g];
            const float nst = tanh_apx(fmaf(rr, s, gi_cur));   // s includes b_hh_n
            const float hv  = fmaf(zz, hreg - nst, nst);       // (1-z)n + z h
            hreg = hv;
            h_s[g] = hv;
            out[step * DD + g] = hv;
        }
        // everyone: h must be written before the next matvec
        asm volatile("bar.sync 2, 384;" ::: "memory");
        gi_cur = gi_next;
    }
}

// ---------------- launch ----------------
extern "C" void kernel_launch(void* const* d_in, const int* in_sizes, int n_in,
                              void* d_out, int out_size) {
    const float* X    = (const float*)d_in[0];
    const float* Wq   = (const float*)d_in[1];
    const float* Wk   = (const float*)d_in[2];
    const float* v    = (const float*)d_in[3];
    const float* w_ih = (const float*)d_in[4];
    const float* w_hh = (const float*)d_in[5];
    const float* b_ih = (const float*)d_in[6];
    const float* b_hh = (const float*)d_in[7];
    float* out = (float*)d_out;

    // fork: prologue (qk -> att+gi) on a side stream; GRU starts immediately on
    // the main stream and consumes gi chunks via epoch flags.
    cudaStream_t s2;
    cudaStreamCreateWithFlags(&s2, cudaStreamNonBlocking);
    cudaEvent_t e1, e2;
    cudaEventCreateWithFlags(&e1, cudaEventDisableTiming);
    cudaEventCreateWithFlags(&e2, cudaEventDisableTiming);

    cudaEventRecord(e1, 0);
    cudaStreamWaitEvent(s2, e1, 0);

    qk_kernel<<<NN / 4, 256, 0, s2>>>(X, Wq, Wk);
    att_gi_kernel<<<NN / 4, 384, 0, s2>>>(X, v, w_ih, b_ih, b_hh);
    cudaEventRecord(e2, s2);

    gru_kernel<<<1, 384>>>(w_hh, b_hh, out);

    cudaStreamWaitEvent(0, e2, 0);
}